// round 8
// baseline (speedup 1.0000x reference)
#include <cuda_runtime.h>
#include <cstdint>

// GCMC layer, algebraically restructured + CSR-ized reduction:
//   G[r][k] = (sum_b att[r,b] basis[b]) @ fc_w[r*192+k*64 .. +64, :]   (1024x256 per (r,k))
//   PreM[n] = cj[n] * (G[r,0][f0(n)] + G[r,1][f1(n)] + G[r,2][f2(n)])  (256-wide)
//   out[d] = fc_b + ci[d] * sum_r sum_{edges->d} PreM_r[src]
// Per-edge reduction via dst-sorted CSR (register accumulation, no output atomics).
// Rating 0 writes (bias folded); ratings 1..4 RMW with the output read hoisted.
// 4 rows per 256-thread CTA in the hot kernels (one 64-lane group per row).
// Feature buffers may be int32 or int64; a device-side probe selects the layout.
// Output layout: [drug_out (50000x256) ; dis_out (50000x256)] fp32.

#define R_RAT 5
#define NN 50000
#define NE 500000
#define IN_U 1024
#define BU 4
#define MU 64
#define OUT_U 256
#define NPR 10            // (phase, rating) streams: 0..4 drug->dis, 5..9 dis->drug
#define ROWS_PER_CTA 4    // NN % ROWS_PER_CTA == 0

// ---- device scratch (static; no runtime allocation) ----
__device__ __align__(16) float g_W[R_RAT * IN_U * MU];          // 1.25 MB
__device__ __align__(16) float g_G[R_RAT * 3 * IN_U * OUT_U];   // 15.7 MB
__device__ __align__(16) float g_PreM[NN * OUT_U];              // 51.2 MB (reused per (phase,r))
__device__ int g_counts [NPR * NN];                             // 2 MB
__device__ int g_offsets[NPR * (NN + 1)];                       // 2 MB
__device__ int g_cursor [NPR * NN];                             // 2 MB
__device__ int g_sortedSrc[(size_t)NPR * NE];                   // 20 MB
__device__ int g_is64[2];                                       // feature dtype flags

// ---------------------------------------------------------------------------
// Probe feature-buffer layout. int64 values < 1024 -> high int32 words == 0.
__global__ void detectFeat64(const int* __restrict__ drugRaw, const int* __restrict__ disRaw) {
    if (blockIdx.x == 0 && threadIdx.x == 0) {
        int a = 0, b = 0;
#pragma unroll
        for (int t = 0; t < 6; t++) {
            a |= __ldg(&drugRaw[2 * t + 1]);
            b |= __ldg(&disRaw [2 * t + 1]);
        }
        g_is64[0] = (a == 0) ? 1 : 0;
        g_is64[1] = (b == 0) ? 1 : 0;
    }
}

// ---------------------------------------------------------------------------
// W[r] = sum_b att[r,b] * basis[b]
__global__ void buildW(const float* __restrict__ att, const float* __restrict__ basis) {
    int idx = blockIdx.x * blockDim.x + threadIdx.x;   // over R*IN_U*MU = 327680
    if (idx >= R_RAT * IN_U * MU) return;
    int r  = idx / (IN_U * MU);
    int ij = idx - r * (IN_U * MU);
    float acc = 0.f;
#pragma unroll
    for (int b = 0; b < BU; b++)
        acc = fmaf(att[r * BU + b], basis[b * (IN_U * MU) + ij], acc);
    g_W[idx] = acc;
}

// ---------------------------------------------------------------------------
// G[r][k] = W[r] @ Frk, Frk = fc_w[r*192 + k*64 + j, :], j in [0,64).
// Two passes over j-halves (jh=0 writes, jh=1 accumulates) to stay under 48KB smem.
__global__ void buildG(const float* __restrict__ fcw, int jh) {
    __shared__ float sF[32 * 256];   // 32 KB
    __shared__ float sW[32];
    int bid = blockIdx.x;            // 5*3*16 = 240 blocks
    int ic = bid & 15;
    int k  = (bid >> 4) % 3;
    int r  = bid / 48;
    int c  = threadIdx.x;

    for (int jj = 0; jj < 32; jj++) {
        int row = r * 192 + k * 64 + jh * 32 + jj;
        sF[jj * 256 + c] = fcw[row * OUT_U + c];
    }
    __syncthreads();

    for (int ii = 0; ii < 64; ii++) {
        int i = ic * 64 + ii;
        __syncthreads();
        if (threadIdx.x < 32)
            sW[threadIdx.x] = g_W[(r * IN_U + i) * MU + jh * 32 + threadIdx.x];
        __syncthreads();
        float acc = 0.f;
#pragma unroll
        for (int jj = 0; jj < 32; jj++)
            acc = fmaf(sW[jj], sF[jj * 256 + c], acc);
        float* gp = &g_G[((size_t)(r * 3 + k) * IN_U + i) * OUT_U + c];
        if (jh) *gp += acc; else *gp = acc;
    }
}

// ---------------------------------------------------------------------------
__global__ void zeroCounts() {
    int i = blockIdx.x * blockDim.x + threadIdx.x;
    if (i < NPR * NN) g_counts[i] = 0;
}

// ---------------------------------------------------------------------------
// All 10 destination histograms in ONE launch. pr<5: dest=dst[r]; else dest=src[r].
__global__ void histAll(const int* __restrict__ src, const int* __restrict__ dst) {
    unsigned idx = blockIdx.x * blockDim.x + threadIdx.x;   // [0, NPR*NE)
    if (idx >= (unsigned)NPR * NE) return;
    unsigned pr = idx / NE;
    unsigned e  = idx - pr * NE;
    int d = (pr < R_RAT) ? __ldg(&dst[(size_t)pr * NE + e])
                         : __ldg(&src[(size_t)(pr - R_RAT) * NE + e]);
    atomicAdd(&g_counts[pr * NN + d], 1);
}

// ---------------------------------------------------------------------------
// One block per pr: sequential-chunk exclusive scan of counts -> offsets, cursor.
__global__ void scanCounts() {
    int pr = blockIdx.x;
    int tid = threadIdx.x;                 // 1024 threads
    int lane = tid & 31, warp = tid >> 5;
    __shared__ int warpSums[32];
    __shared__ int carry;
    if (tid == 0) carry = 0;
    __syncthreads();

    for (int base = 0; base < NN; base += 1024) {
        int i = base + tid;
        int v = (i < NN) ? g_counts[pr * NN + i] : 0;
        int x = v;
#pragma unroll
        for (int o = 1; o < 32; o <<= 1) {
            int y = __shfl_up_sync(0xFFFFFFFFu, x, o);
            if (lane >= o) x += y;
        }
        if (lane == 31) warpSums[warp] = x;
        __syncthreads();
        if (tid < 32) {
            int s = warpSums[tid];
#pragma unroll
            for (int o = 1; o < 32; o <<= 1) {
                int y = __shfl_up_sync(0xFFFFFFFFu, s, o);
                if (tid >= o) s += y;
            }
            warpSums[tid] = s;
        }
        __syncthreads();
        int incl = x + (warp ? warpSums[warp - 1] : 0);
        int total = warpSums[31];
        if (i < NN) {
            int off = carry + incl - v;       // exclusive
            g_offsets[pr * (NN + 1) + i] = off;
            g_cursor [pr * NN + i] = off;
        }
        __syncthreads();
        if (tid == 0) carry += total;
        __syncthreads();
    }
    if (tid == 0) g_offsets[pr * (NN + 1) + NN] = carry;
}

// ---------------------------------------------------------------------------
// All 10 CSR fills in ONE launch. pr<5: (dest,val)=(dst,src); else (src,dst).
__global__ void fillAll(const int* __restrict__ src, const int* __restrict__ dst) {
    unsigned idx = blockIdx.x * blockDim.x + threadIdx.x;   // [0, NPR*NE)
    if (idx >= (unsigned)NPR * NE) return;
    unsigned pr = idx / NE;
    unsigned e  = idx - pr * NE;
    int d, s;
    if (pr < R_RAT) {
        d = __ldg(&dst[(size_t)pr * NE + e]);
        s = __ldg(&src[(size_t)pr * NE + e]);
    } else {
        d = __ldg(&src[(size_t)(pr - R_RAT) * NE + e]);
        s = __ldg(&dst[(size_t)(pr - R_RAT) * NE + e]);
    }
    int pos = atomicAdd(&g_cursor[pr * NN + d], 1);
    g_sortedSrc[(size_t)pr * NE + pos] = s;
}

// ---------------------------------------------------------------------------
// PreM[n] = cj[n] * (G[r,0][f0] + G[r,1][f1] + G[r,2][f2]).
// 256-thread CTA = 4 rows; each 64-lane group handles one row (float4 lanes).
__global__ void __launch_bounds__(256) preMsg(const void* __restrict__ feat,
                                              const float* __restrict__ cj,
                                              int r, int phase) {
    int n = blockIdx.x * ROWS_PER_CTA + (threadIdx.x >> 6);
    int lane = threadIdx.x & 63;            // 0..63, one float4 each
    int f0, f1, f2;
    if (g_is64[phase]) {
        const long long* fp = (const long long*)feat;
        f0 = (int)__ldg(&fp[n * 3 + 0]);
        f1 = (int)__ldg(&fp[n * 3 + 1]);
        f2 = (int)__ldg(&fp[n * 3 + 2]);
    } else {
        const int* fp = (const int*)feat;
        f0 = __ldg(&fp[n * 3 + 0]);
        f1 = __ldg(&fp[n * 3 + 1]);
        f2 = __ldg(&fp[n * 3 + 2]);
    }
    float cjv = __ldg(&cj[n]);
    const float4 v0 = *reinterpret_cast<const float4*>(
        &g_G[((size_t)(r * 3 + 0) * IN_U + f0) * OUT_U + lane * 4]);
    const float4 v1 = *reinterpret_cast<const float4*>(
        &g_G[((size_t)(r * 3 + 1) * IN_U + f1) * OUT_U + lane * 4]);
    const float4 v2 = *reinterpret_cast<const float4*>(
        &g_G[((size_t)(r * 3 + 2) * IN_U + f2) * OUT_U + lane * 4]);
    float4 o;
    o.x = cjv * (v0.x + v1.x + v2.x);
    o.y = cjv * (v0.y + v1.y + v2.y);
    o.z = cjv * (v0.z + v1.z + v2.z);
    o.w = cjv * (v0.w + v1.w + v2.w);
    *reinterpret_cast<float4*>(&g_PreM[(size_t)n * OUT_U + lane * 4]) = o;
}

// ---------------------------------------------------------------------------
// 256-thread CTA = 4 destination rows; each 64-lane group accumulates one row.
// Unroll-4: 4 independent accumulators -> >=4 outstanding 128B loads per thread.
// Output/bias read and ci[d] issued BEFORE the gather loop (latency overlap).
// FIRST==1 (rating 0): out = fc_b + ci*acc (pure write). FIRST==0: out += ci*acc.
template <int FIRST>
__global__ void __launch_bounds__(256) gatherRows(int pr, const float* __restrict__ ci,
                                                  const float* __restrict__ fcb,
                                                  float* __restrict__ outSide) {
    int d = blockIdx.x * ROWS_PER_CTA + (threadIdx.x >> 6);
    int lane = threadIdx.x & 63;            // 0..63
    int beg = __ldg(&g_offsets[pr * (NN + 1) + d]);
    int end = __ldg(&g_offsets[pr * (NN + 1) + d + 1]);
    const int* sl = &g_sortedSrc[(size_t)pr * NE];

    float civ = __ldg(&ci[d]);
    float4* op = reinterpret_cast<float4*>(&outSide[(size_t)d * OUT_U + lane * 4]);
    float4 base;
    if (FIRST) base = *reinterpret_cast<const float4*>(&fcb[lane * 4]);
    else       base = *op;

    float4 a0 = {0.f, 0.f, 0.f, 0.f};
    float4 a1 = {0.f, 0.f, 0.f, 0.f};
    float4 a2 = {0.f, 0.f, 0.f, 0.f};
    float4 a3 = {0.f, 0.f, 0.f, 0.f};
    int j = beg;
    for (; j + 3 < end; j += 4) {
        int s0 = __ldg(&sl[j]);
        int s1 = __ldg(&sl[j + 1]);
        int s2 = __ldg(&sl[j + 2]);
        int s3 = __ldg(&sl[j + 3]);
        float4 v0 = *reinterpret_cast<const float4*>(&g_PreM[(size_t)s0 * OUT_U + lane * 4]);
        float4 v1 = *reinterpret_cast<const float4*>(&g_PreM[(size_t)s1 * OUT_U + lane * 4]);
        float4 v2 = *reinterpret_cast<const float4*>(&g_PreM[(size_t)s2 * OUT_U + lane * 4]);
        float4 v3 = *reinterpret_cast<const float4*>(&g_PreM[(size_t)s3 * OUT_U + lane * 4]);
        a0.x += v0.x; a0.y += v0.y; a0.z += v0.z; a0.w += v0.w;
        a1.x += v1.x; a1.y += v1.y; a1.z += v1.z; a1.w += v1.w;
        a2.x += v2.x; a2.y += v2.y; a2.z += v2.z; a2.w += v2.w;
        a3.x += v3.x; a3.y += v3.y; a3.z += v3.z; a3.w += v3.w;
    }
    for (; j < end; j++) {
        int s0 = __ldg(&sl[j]);
        float4 v0 = *reinterpret_cast<const float4*>(&g_PreM[(size_t)s0 * OUT_U + lane * 4]);
        a0.x += v0.x; a0.y += v0.y; a0.z += v0.z; a0.w += v0.w;
    }
    a0.x += a1.x; a0.y += a1.y; a0.z += a1.z; a0.w += a1.w;
    a2.x += a3.x; a2.y += a3.y; a2.z += a3.z; a2.w += a3.w;
    a0.x += a2.x; a0.y += a2.y; a0.z += a2.z; a0.w += a2.w;

    float4 o;
    o.x = base.x + civ * a0.x; o.y = base.y + civ * a0.y;
    o.z = base.z + civ * a0.z; o.w = base.w + civ * a0.w;
    *op = o;
}

// ---------------------------------------------------------------------------
extern "C" void kernel_launch(void* const* d_in, const int* in_sizes, int n_in,
                              void* d_out, int out_size) {
    const void*  drug_feat = d_in[0];                 // [NN,3] int32 or int64
    const void*  dis_feat  = d_in[1];                 // [NN,3] int32 or int64
    const int*   src       = (const int*)  d_in[2];   // [R,NE]
    const int*   dst       = (const int*)  d_in[3];   // [R,NE]
    const float* cj_drug   = (const float*)d_in[4];
    const float* ci_drug   = (const float*)d_in[5];
    const float* cj_dis    = (const float*)d_in[6];
    const float* ci_dis    = (const float*)d_in[7];
    const float* att       = (const float*)d_in[8];   // [R,BU]
    const float* basis     = (const float*)d_in[9];   // [BU,IN_U,MU]
    const float* fc_w      = (const float*)d_in[10];  // [3*MU*R, OUT_U]
    const float* fc_b      = (const float*)d_in[11];  // [OUT_U]
    float* out = (float*)d_out;                       // [2*NN, OUT_U]: drug then dis

    // --- feature-layout probe + dense precompute ---
    detectFeat64<<<1, 32>>>((const int*)drug_feat, (const int*)dis_feat);
    buildW<<<(R_RAT * IN_U * MU + 255) / 256, 256>>>(att, basis);
    buildG<<<R_RAT * 3 * 16, 256>>>(fc_w, 0);
    buildG<<<R_RAT * 3 * 16, 256>>>(fc_w, 1);

    // --- CSR build for all 10 (phase, rating) streams: 4 launches total ---
    zeroCounts<<<(NPR * NN + 255) / 256, 256>>>();
    const unsigned ag = (unsigned)(((size_t)NPR * NE + 255) / 256);
    histAll<<<ag, 256>>>(src, dst);
    scanCounts<<<NPR, 1024>>>();
    fillAll<<<ag, 256>>>(src, dst);

    const int rowGrid = NN / ROWS_PER_CTA;   // 12500 CTAs, 256 threads

    // --- Phase 1: drug -> dis (output = dis half) ---
    float* outDis = out + (size_t)NN * OUT_U;
    for (int r = 0; r < R_RAT; r++) {
        preMsg<<<rowGrid, 256>>>(drug_feat, cj_drug, r, 0);
        if (r == 0) gatherRows<1><<<rowGrid, 256>>>(r, ci_dis, fc_b, outDis);
        else        gatherRows<0><<<rowGrid, 256>>>(r, ci_dis, fc_b, outDis);
    }
    // --- Phase 2: dis -> drug (output = drug half) ---
    for (int r = 0; r < R_RAT; r++) {
        preMsg<<<rowGrid, 256>>>(dis_feat, cj_dis, r, 1);
        if (r == 0) gatherRows<1><<<rowGrid, 256>>>(r + R_RAT, ci_drug, fc_b, out);
        else        gatherRows<0><<<rowGrid, 256>>>(r + R_RAT, ci_drug, fc_b, out);
    }
}

// round 10
// speedup vs baseline: 1.0463x; 1.0463x over previous
#include <cuda_runtime.h>
#include <cstdint>

// GCMC layer, algebraically restructured + CSR-ized reduction:
//   G[r][k] = (sum_b att[r,b] basis[b]) @ fc_w[r*192+k*64 .. +64, :]   (1024x256 per (r,k))
//   PreM[n] = cj[n] * (G[r,0][f0(n)] + G[r,1][f1(n)] + G[r,2][f2(n)])  (256-wide)
//   out[d] = fc_b + ci[d] * sum_r sum_{edges->d} PreM_r[src]
// Per-edge reduction via dst-sorted CSR (register accumulation, no output atomics).
// Rating 0 writes (bias folded); ratings 1..4 RMW with the output read hoisted.
// 4 rows per 256-thread CTA in the hot kernels (one 64-lane group per row).
// buildG: single-launch register-accumulator GEMM (R8 ncu: old version was
// barrier-bound at 2x60us, fma=5.7%, occ=19.7%).
// Feature buffers may be int32 or int64; a device-side probe selects the layout.
// Output layout: [drug_out (50000x256) ; dis_out (50000x256)] fp32.

#define R_RAT 5
#define NN 50000
#define NE 500000
#define IN_U 1024
#define BU 4
#define MU 64
#define OUT_U 256
#define NPR 10            // (phase, rating) streams: 0..4 drug->dis, 5..9 dis->drug
#define ROWS_PER_CTA 4    // NN % ROWS_PER_CTA == 0

// ---- device scratch (static; no runtime allocation) ----
__device__ __align__(16) float g_W[R_RAT * IN_U * MU];          // 1.25 MB
__device__ __align__(16) float g_G[R_RAT * 3 * IN_U * OUT_U];   // 15.7 MB
__device__ __align__(16) float g_PreM[NN * OUT_U];              // 51.2 MB (reused per (phase,r))
__device__ int g_counts [NPR * NN];                             // 2 MB
__device__ int g_offsets[NPR * (NN + 1)];                       // 2 MB
__device__ int g_cursor [NPR * NN];                             // 2 MB
__device__ int g_sortedSrc[(size_t)NPR * NE];                   // 20 MB
__device__ int g_is64[2];                                       // feature dtype flags

// ---------------------------------------------------------------------------
// Probe feature-buffer layout. int64 values < 1024 -> high int32 words == 0.
__global__ void detectFeat64(const int* __restrict__ drugRaw, const int* __restrict__ disRaw) {
    if (blockIdx.x == 0 && threadIdx.x == 0) {
        int a = 0, b = 0;
#pragma unroll
        for (int t = 0; t < 6; t++) {
            a |= __ldg(&drugRaw[2 * t + 1]);
            b |= __ldg(&disRaw [2 * t + 1]);
        }
        g_is64[0] = (a == 0) ? 1 : 0;
        g_is64[1] = (b == 0) ? 1 : 0;
    }
}

// ---------------------------------------------------------------------------
// W[r] = sum_b att[r,b] * basis[b]
__global__ void buildW(const float* __restrict__ att, const float* __restrict__ basis) {
    int idx = blockIdx.x * blockDim.x + threadIdx.x;   // over R*IN_U*MU = 327680
    if (idx >= R_RAT * IN_U * MU) return;
    int r  = idx / (IN_U * MU);
    int ij = idx - r * (IN_U * MU);
    float acc = 0.f;
#pragma unroll
    for (int b = 0; b < BU; b++)
        acc = fmaf(att[r * BU + b], basis[b * (IN_U * MU) + ij], acc);
    g_W[idx] = acc;
}

// ---------------------------------------------------------------------------
// G[r][k] = W[r](rows, K=64) @ fc_w[r*192+k*64 .. +64, :]  (register accumulators)
// Block = (r, k, 32-row chunk): 480 blocks x 256 threads; thread owns column c
// and 32 row-accumulators. One smem load + one sync; K-loop has no barriers.
__global__ void __launch_bounds__(256) buildG(const float* __restrict__ fcw) {
    __shared__ float sWT[64][33];    // transposed W chunk: sWT[k][i], 32 rows, 8.4 KB
    int bid = blockIdx.x;            // 15 * 32 = 480 blocks
    int ic = bid & 31;               // 32-row chunk
    int k  = (bid >> 5) % 3;
    int r  = bid / 96;
    int c  = threadIdx.x;            // output column 0..255

    // Cooperative load: 32 rows x 64 K = 2048 floats, 8 per thread.
    for (int t = c; t < 32 * 64; t += 256) {
        int i  = t >> 6;             // row-in-chunk
        int kk = t & 63;
        sWT[kk][i] = g_W[((size_t)r * IN_U + ic * 32 + i) * MU + kk];
    }
    __syncthreads();

    float acc[32];
#pragma unroll
    for (int i = 0; i < 32; i++) acc[i] = 0.f;

    const float* B = &fcw[(size_t)(r * 192 + k * 64) * OUT_U + c];
    for (int kk = 0; kk < 64; kk++) {
        float b = __ldg(&B[(size_t)kk * OUT_U]);
#pragma unroll
        for (int i = 0; i < 32; i++)
            acc[i] = fmaf(sWT[kk][i], b, acc[i]);
    }

    float* gp = &g_G[(((size_t)(r * 3 + k)) * IN_U + ic * 32) * OUT_U + c];
#pragma unroll
    for (int i = 0; i < 32; i++)
        gp[(size_t)i * OUT_U] = acc[i];
}

// ---------------------------------------------------------------------------
__global__ void zeroCounts() {
    int i = blockIdx.x * blockDim.x + threadIdx.x;
    if (i < NPR * NN) g_counts[i] = 0;
}

// ---------------------------------------------------------------------------
// All 10 destination histograms in ONE launch. pr<5: dest=dst[r]; else dest=src[r].
__global__ void histAll(const int* __restrict__ src, const int* __restrict__ dst) {
    unsigned idx = blockIdx.x * blockDim.x + threadIdx.x;   // [0, NPR*NE)
    if (idx >= (unsigned)NPR * NE) return;
    unsigned pr = idx / NE;
    unsigned e  = idx - pr * NE;
    int d = (pr < R_RAT) ? __ldg(&dst[(size_t)pr * NE + e])
                         : __ldg(&src[(size_t)(pr - R_RAT) * NE + e]);
    atomicAdd(&g_counts[pr * NN + d], 1);
}

// ---------------------------------------------------------------------------
// One block per pr: sequential-chunk exclusive scan of counts -> offsets, cursor.
__global__ void scanCounts() {
    int pr = blockIdx.x;
    int tid = threadIdx.x;                 // 1024 threads
    int lane = tid & 31, warp = tid >> 5;
    __shared__ int warpSums[32];
    __shared__ int carry;
    if (tid == 0) carry = 0;
    __syncthreads();

    for (int base = 0; base < NN; base += 1024) {
        int i = base + tid;
        int v = (i < NN) ? g_counts[pr * NN + i] : 0;
        int x = v;
#pragma unroll
        for (int o = 1; o < 32; o <<= 1) {
            int y = __shfl_up_sync(0xFFFFFFFFu, x, o);
            if (lane >= o) x += y;
        }
        if (lane == 31) warpSums[warp] = x;
        __syncthreads();
        if (tid < 32) {
            int s = warpSums[tid];
#pragma unroll
            for (int o = 1; o < 32; o <<= 1) {
                int y = __shfl_up_sync(0xFFFFFFFFu, s, o);
                if (tid >= o) s += y;
            }
            warpSums[tid] = s;
        }
        __syncthreads();
        int incl = x + (warp ? warpSums[warp - 1] : 0);
        int total = warpSums[31];
        if (i < NN) {
            int off = carry + incl - v;       // exclusive
            g_offsets[pr * (NN + 1) + i] = off;
            g_cursor [pr * NN + i] = off;
        }
        __syncthreads();
        if (tid == 0) carry += total;
        __syncthreads();
    }
    if (tid == 0) g_offsets[pr * (NN + 1) + NN] = carry;
}

// ---------------------------------------------------------------------------
// All 10 CSR fills in ONE launch. pr<5: (dest,val)=(dst,src); else (src,dst).
__global__ void fillAll(const int* __restrict__ src, const int* __restrict__ dst) {
    unsigned idx = blockIdx.x * blockDim.x + threadIdx.x;   // [0, NPR*NE)
    if (idx >= (unsigned)NPR * NE) return;
    unsigned pr = idx / NE;
    unsigned e  = idx - pr * NE;
    int d, s;
    if (pr < R_RAT) {
        d = __ldg(&dst[(size_t)pr * NE + e]);
        s = __ldg(&src[(size_t)pr * NE + e]);
    } else {
        d = __ldg(&src[(size_t)(pr - R_RAT) * NE + e]);
        s = __ldg(&dst[(size_t)(pr - R_RAT) * NE + e]);
    }
    int pos = atomicAdd(&g_cursor[pr * NN + d], 1);
    g_sortedSrc[(size_t)pr * NE + pos] = s;
}

// ---------------------------------------------------------------------------
// PreM[n] = cj[n] * (G[r,0][f0] + G[r,1][f1] + G[r,2][f2]).
// 256-thread CTA = 4 rows; each 64-lane group handles one row (float4 lanes).
__global__ void __launch_bounds__(256) preMsg(const void* __restrict__ feat,
                                              const float* __restrict__ cj,
                                              int r, int phase) {
    int n = blockIdx.x * ROWS_PER_CTA + (threadIdx.x >> 6);
    int lane = threadIdx.x & 63;            // 0..63, one float4 each
    int f0, f1, f2;
    if (g_is64[phase]) {
        const long long* fp = (const long long*)feat;
        f0 = (int)__ldg(&fp[n * 3 + 0]);
        f1 = (int)__ldg(&fp[n * 3 + 1]);
        f2 = (int)__ldg(&fp[n * 3 + 2]);
    } else {
        const int* fp = (const int*)feat;
        f0 = __ldg(&fp[n * 3 + 0]);
        f1 = __ldg(&fp[n * 3 + 1]);
        f2 = __ldg(&fp[n * 3 + 2]);
    }
    float cjv = __ldg(&cj[n]);
    const float4 v0 = *reinterpret_cast<const float4*>(
        &g_G[((size_t)(r * 3 + 0) * IN_U + f0) * OUT_U + lane * 4]);
    const float4 v1 = *reinterpret_cast<const float4*>(
        &g_G[((size_t)(r * 3 + 1) * IN_U + f1) * OUT_U + lane * 4]);
    const float4 v2 = *reinterpret_cast<const float4*>(
        &g_G[((size_t)(r * 3 + 2) * IN_U + f2) * OUT_U + lane * 4]);
    float4 o;
    o.x = cjv * (v0.x + v1.x + v2.x);
    o.y = cjv * (v0.y + v1.y + v2.y);
    o.z = cjv * (v0.z + v1.z + v2.z);
    o.w = cjv * (v0.w + v1.w + v2.w);
    *reinterpret_cast<float4*>(&g_PreM[(size_t)n * OUT_U + lane * 4]) = o;
}

// ---------------------------------------------------------------------------
// 256-thread CTA = 4 destination rows; each 64-lane group accumulates one row.
// Unroll-4: 4 independent accumulators -> >=4 outstanding 128B loads per thread.
// Output/bias read and ci[d] issued BEFORE the gather loop (latency overlap).
// FIRST==1 (rating 0): out = fc_b + ci*acc (pure write). FIRST==0: out += ci*acc.
template <int FIRST>
__global__ void __launch_bounds__(256) gatherRows(int pr, const float* __restrict__ ci,
                                                  const float* __restrict__ fcb,
                                                  float* __restrict__ outSide) {
    int d = blockIdx.x * ROWS_PER_CTA + (threadIdx.x >> 6);
    int lane = threadIdx.x & 63;            // 0..63
    int beg = __ldg(&g_offsets[pr * (NN + 1) + d]);
    int end = __ldg(&g_offsets[pr * (NN + 1) + d + 1]);
    const int* sl = &g_sortedSrc[(size_t)pr * NE];

    float civ = __ldg(&ci[d]);
    float4* op = reinterpret_cast<float4*>(&outSide[(size_t)d * OUT_U + lane * 4]);
    float4 base;
    if (FIRST) base = *reinterpret_cast<const float4*>(&fcb[lane * 4]);
    else       base = *op;

    float4 a0 = {0.f, 0.f, 0.f, 0.f};
    float4 a1 = {0.f, 0.f, 0.f, 0.f};
    float4 a2 = {0.f, 0.f, 0.f, 0.f};
    float4 a3 = {0.f, 0.f, 0.f, 0.f};
    int j = beg;
    for (; j + 3 < end; j += 4) {
        int s0 = __ldg(&sl[j]);
        int s1 = __ldg(&sl[j + 1]);
        int s2 = __ldg(&sl[j + 2]);
        int s3 = __ldg(&sl[j + 3]);
        float4 v0 = *reinterpret_cast<const float4*>(&g_PreM[(size_t)s0 * OUT_U + lane * 4]);
        float4 v1 = *reinterpret_cast<const float4*>(&g_PreM[(size_t)s1 * OUT_U + lane * 4]);
        float4 v2 = *reinterpret_cast<const float4*>(&g_PreM[(size_t)s2 * OUT_U + lane * 4]);
        float4 v3 = *reinterpret_cast<const float4*>(&g_PreM[(size_t)s3 * OUT_U + lane * 4]);
        a0.x += v0.x; a0.y += v0.y; a0.z += v0.z; a0.w += v0.w;
        a1.x += v1.x; a1.y += v1.y; a1.z += v1.z; a1.w += v1.w;
        a2.x += v2.x; a2.y += v2.y; a2.z += v2.z; a2.w += v2.w;
        a3.x += v3.x; a3.y += v3.y; a3.z += v3.z; a3.w += v3.w;
    }
    for (; j < end; j++) {
        int s0 = __ldg(&sl[j]);
        float4 v0 = *reinterpret_cast<const float4*>(&g_PreM[(size_t)s0 * OUT_U + lane * 4]);
        a0.x += v0.x; a0.y += v0.y; a0.z += v0.z; a0.w += v0.w;
    }
    a0.x += a1.x; a0.y += a1.y; a0.z += a1.z; a0.w += a1.w;
    a2.x += a3.x; a2.y += a3.y; a2.z += a3.z; a2.w += a3.w;
    a0.x += a2.x; a0.y += a2.y; a0.z += a2.z; a0.w += a2.w;

    float4 o;
    o.x = base.x + civ * a0.x; o.y = base.y + civ * a0.y;
    o.z = base.z + civ * a0.z; o.w = base.w + civ * a0.w;
    *op = o;
}

// ---------------------------------------------------------------------------
extern "C" void kernel_launch(void* const* d_in, const int* in_sizes, int n_in,
                              void* d_out, int out_size) {
    const void*  drug_feat = d_in[0];                 // [NN,3] int32 or int64
    const void*  dis_feat  = d_in[1];                 // [NN,3] int32 or int64
    const int*   src       = (const int*)  d_in[2];   // [R,NE]
    const int*   dst       = (const int*)  d_in[3];   // [R,NE]
    const float* cj_drug   = (const float*)d_in[4];
    const float* ci_drug   = (const float*)d_in[5];
    const float* cj_dis    = (const float*)d_in[6];
    const float* ci_dis    = (const float*)d_in[7];
    const float* att       = (const float*)d_in[8];   // [R,BU]
    const float* basis     = (const float*)d_in[9];   // [BU,IN_U,MU]
    const float* fc_w      = (const float*)d_in[10];  // [3*MU*R, OUT_U]
    const float* fc_b      = (const float*)d_in[11];  // [OUT_U]
    float* out = (float*)d_out;                       // [2*NN, OUT_U]: drug then dis

    // --- feature-layout probe + dense precompute ---
    detectFeat64<<<1, 32>>>((const int*)drug_feat, (const int*)dis_feat);
    buildW<<<(R_RAT * IN_U * MU + 255) / 256, 256>>>(att, basis);
    buildG<<<480, 256>>>(fc_w);

    // --- CSR build for all 10 (phase, rating) streams: 4 launches total ---
    zeroCounts<<<(NPR * NN + 255) / 256, 256>>>();
    const unsigned ag = (unsigned)(((size_t)NPR * NE + 255) / 256);
    histAll<<<ag, 256>>>(src, dst);
    scanCounts<<<NPR, 1024>>>();
    fillAll<<<ag, 256>>>(src, dst);

    const int rowGrid = NN / ROWS_PER_CTA;   // 12500 CTAs, 256 threads

    // --- Phase 1: drug -> dis (output = dis half) ---
    float* outDis = out + (size_t)NN * OUT_U;
    for (int r = 0; r < R_RAT; r++) {
        preMsg<<<rowGrid, 256>>>(drug_feat, cj_drug, r, 0);
        if (r == 0) gatherRows<1><<<rowGrid, 256>>>(r, ci_dis, fc_b, outDis);
        else        gatherRows<0><<<rowGrid, 256>>>(r, ci_dis, fc_b, outDis);
    }
    // --- Phase 2: dis -> drug (output = drug half) ---
    for (int r = 0; r < R_RAT; r++) {
        preMsg<<<rowGrid, 256>>>(dis_feat, cj_dis, r, 1);
        if (r == 0) gatherRows<1><<<rowGrid, 256>>>(r + R_RAT, ci_drug, fc_b, out);
        else        gatherRows<0><<<rowGrid, 256>>>(r + R_RAT, ci_drug, fc_b, out);
    }
}